// round 13
// baseline (speedup 1.0000x reference)
#include <cuda_runtime.h>
#include <cuda_fp16.h>
#include <mma.h>

using namespace nvcuda;

#define NMAX    50000
#define NPADMAX 50176   // ceil(50000/128)*128
#define HD      128
#define EMAX    800000
#define ELLW    96      // ELL row width; P(in-deg >= 96) ~ 1e-25 for Poisson(16)

// ---------------- device scratch (no allocations allowed) ----------------
// g_ints: [0,N): out-degree (src); [NMAX, NMAX+N): ELL in-counts (dst)
__device__ int    g_ints[2 * NMAX];
__device__ int    g_ell[(size_t)NMAX * ELLW];  // ELL: src indices grouped by dst
// combined fp16 gate weights: [0]=top (k<128: W00|W20), [1]=bot (W01|W21); 128x256 each
__device__ __half g_Wcomb[2 * 128 * 256];
__device__ float  g_biasf2[256];               // folded biases [z cols | h cols]
__device__ float  g_P[(size_t)NPADMAX * 256];  // P = Xh@Wtop + bias (fp32)
__device__ __half g_Xhh[(size_t)NPADMAX * HD]; // fp16 Xh
__device__ __half g_LXh[(size_t)NPADMAX * HD]; // fp16 LX = L_hat @ Xh
__device__ __half g_hh [(size_t)NPADMAX * HD]; // fp16 h for decoder

// ---------------- helpers ----------------
__device__ __forceinline__ void st4h(__half* p, float4 v) {
    __half2 a = __floats2half2_rn(v.x, v.y);
    __half2 b = __floats2half2_rn(v.z, v.w);
    uint2 o;
    o.x = *(unsigned*)&a;
    o.y = *(unsigned*)&b;
    *(uint2*)p = o;
}

// edge buffers are declared int64 in the reference, but JAX without x64
// silently yields int32. 32 lanes x 2 int64 reads + ballot: random int32
// pairs combine to values >= N with overwhelming probability.
__device__ __forceinline__ int detect64_warp(const void* p, int n_nodes, int lane) {
    const long long* q = (const long long*)p;
    long long v0 = q[lane];
    long long v1 = q[32 + lane];
    int ok = (v0 >= 0) && (v0 < (long long)n_nodes) &&
             (v1 >= 0) && (v1 < (long long)n_nodes);
    return __all_sync(0xFFFFFFFFu, ok);
}

__device__ __forceinline__ long long ld_idx(const void* p, long long i, int is64) {
    if (is64) return ((const long long*)p)[i];
    return (long long)((const int*)p)[i];
}

// ---------------- ELL build: out-degree + grouped-by-dst src lists, one pass ----
__global__ void fill_ell(const void* __restrict__ ei, int E, int n_nodes) {
    __shared__ int sh64;
    if (threadIdx.x < 32) {
        int ok = detect64_warp(ei, n_nodes, threadIdx.x);
        if (threadIdx.x == 0) sh64 = ok;
    }
    __syncthreads();
    int is64 = sh64;
    int e = blockIdx.x * blockDim.x + threadIdx.x;
    if (e < E) {
        long long s = ld_idx(ei, e, is64);
        long long d = ld_idx(ei, (long long)E + e, is64);
        atomicAdd(&g_ints[s], 1);                       // out-degree
        int slot = atomicAdd(&g_ints[NMAX + d], 1);     // in-count / ELL cursor
        if (slot < ELLW) g_ell[(size_t)d * ELLW + slot] = (int)s;
    }
}

// ---------------- SpMM: LXh[d] = sum -(dinv[s]*dinv[d]) * Xhh[s]  --------------
// warp per row; unroll-8 MLP; 32-bit addressing; dinv inline from out-degree.
#define SPMM_GRP(K) \
    { int s_ = row[j + K]; \
      w_[K] = rsqrtf((float)g_ints[s_]); \
      v_[K] = Xb[(unsigned)(s_ * 32 + lane)]; }
#define SPMM_ACC(K) \
    { float2 f0_ = __half22float2(*(__half2*)&v_[K].x); \
      float2 f1_ = __half22float2(*(__half2*)&v_[K].y); \
      float w__ = dv * w_[K]; \
      acc.x += w__ * f0_.x; acc.y += w__ * f0_.y; \
      acc.z += w__ * f1_.x; acc.w += w__ * f1_.y; }
__global__ void __launch_bounds__(256)
spmm_ell(int n, int npad) {
    int gw = (blockIdx.x * blockDim.x + threadIdx.x) >> 5;
    int lane = threadIdx.x & 31;
    if (gw >= npad) return;
    float4 acc = make_float4(0.f, 0.f, 0.f, 0.f);
    if (gw < n) {
        int od = g_ints[gw];
        float dv = (od > 0) ? -rsqrtf((float)od) : 0.0f;
        int len = g_ints[NMAX + gw];
        if (len > ELLW) len = ELLW;
        const int* row = &g_ell[(size_t)gw * ELLW];
        const uint2* Xb = (const uint2*)g_Xhh;
        float w_[8];
        uint2 v_[8];
        int j = 0;
        for (; j + 7 < len; j += 8) {
            SPMM_GRP(0) SPMM_GRP(1) SPMM_GRP(2) SPMM_GRP(3)
            SPMM_GRP(4) SPMM_GRP(5) SPMM_GRP(6) SPMM_GRP(7)
            SPMM_ACC(0) SPMM_ACC(1) SPMM_ACC(2) SPMM_ACC(3)
            SPMM_ACC(4) SPMM_ACC(5) SPMM_ACC(6) SPMM_ACC(7)
        }
        for (; j + 3 < len; j += 4) {
            SPMM_GRP(0) SPMM_GRP(1) SPMM_GRP(2) SPMM_GRP(3)
            SPMM_ACC(0) SPMM_ACC(1) SPMM_ACC(2) SPMM_ACC(3)
        }
        for (; j < len; j++) {
            int s = row[j];
            float w = dv * rsqrtf((float)g_ints[s]);
            uint2 val = Xb[(unsigned)(s * 32 + lane)];
            float2 f0 = __half22float2(*(__half2*)&val.x);
            float2 f1 = __half22float2(*(__half2*)&val.y);
            acc.x += w * f0.x; acc.y += w * f0.y;
            acc.z += w * f1.x; acc.w += w * f1.y;
        }
    }
    st4h(&g_LXh[(size_t)gw * HD + lane * 4], acc);
}

// ---------------- fp16 GEMM: Xhh = fp16(x @ pre_w + pre_b); also converts gate
// weights (blocks 0..64) so gemm_P (next on s2) sees fp16 weights + biases. ------
#define PRE_SMEM (34816 + 34816 + 8704)
__global__ void __launch_bounds__(256)
gemm_pre_fp16(const float* __restrict__ x, const float* __restrict__ W,
              const float* __restrict__ bias,
              const float* __restrict__ Wx, const float* __restrict__ bx,
              const float* __restrict__ bh, int n) {
    extern __shared__ char smc[];
    __half* As  = (__half*)smc;             // 128 x 136 half
    __half* Bs  = (__half*)(smc + 34816);   // 128 x 136 half
    float* Bias = (float*)(smc + 69632);    // 16 x 136 float
    float* Stg  = (float*)smc;              // epilogue stage: 128 x 136 float (reuse)
    int t = threadIdx.x;
    int row0 = blockIdx.x * 128;

    // prologue: gate-weight fp32->fp16 convert + bias fold (blocks 0..64)
    if (blockIdx.x < 64) {
        int idx = blockIdx.x * 256 + t;       // 0..16383 float4
        int which = idx >> 13;                // 0=top(c=0), 1=bot(c=1)
        int rem = idx & 8191;
        int r = rem >> 6, c4 = rem & 63;
        int ncol = c4 * 4;
        int gate = (ncol >= 128);             // 0=z(W0x), 1=h(W2x)
        size_t base4 = ((size_t)((gate ? 4 : 0) + which)) * 4096;  // float4 units
        float4 v = ((const float4*)Wx)[base4 + r * 32 + (c4 & 31)];
        st4h(&g_Wcomb[(size_t)which * 32768 + r * 256 + ncol], v);
    } else if (blockIdx.x == 64 && t < 256) {
        int ncol = t;
        int gate = (ncol >= 128);
        g_biasf2[ncol] = bx[(gate ? 2 : 0) * 128 + (ncol & 127)]
                       + bh[(gate ? 2 : 0) * 128 + (ncol & 127)];
    }

    const float4* x4 = (const float4*)x;
    #pragma unroll
    for (int i = 0; i < 16; i++) {
        int idx = t + i * 256;
        int r = idx >> 5, c = idx & 31;
        float4 v = make_float4(0.f, 0.f, 0.f, 0.f);
        if (row0 + r < n) v = x4[(size_t)(row0 + r) * 32 + c];
        st4h(&As[r * 136 + c * 4], v);
    }
    const float4* W4 = (const float4*)W;
    #pragma unroll
    for (int i = 0; i < 16; i++) {
        int idx = t + i * 256;
        int r = idx >> 5, c = idx & 31;
        st4h(&Bs[r * 136 + c * 4], W4[idx]);
    }
    #pragma unroll
    for (int i = 0; i < 8; i++) {
        int idx = t + i * 256;
        int r = idx >> 7, c = idx & 127;
        Bias[r * 136 + c] = bias[c];
    }
    __syncthreads();

    int warp = t >> 5;
    int wr = warp & 3, wc = warp >> 2;

    wmma::fragment<wmma::accumulator, 16, 16, 16, float> acc[2][4];
    #pragma unroll
    for (int i = 0; i < 2; i++)
        #pragma unroll
        for (int j = 0; j < 4; j++)
            wmma::load_matrix_sync(acc[i][j], &Bias[wc * 64 + j * 16], 136,
                                   wmma::mem_row_major);

    #pragma unroll
    for (int k = 0; k < 128; k += 16) {
        wmma::fragment<wmma::matrix_a, 16, 16, 16, __half, wmma::row_major> af[2];
        wmma::fragment<wmma::matrix_b, 16, 16, 16, __half, wmma::row_major> bf[4];
        #pragma unroll
        for (int i = 0; i < 2; i++)
            wmma::load_matrix_sync(af[i], &As[(wr * 32 + i * 16) * 136 + k], 136);
        #pragma unroll
        for (int j = 0; j < 4; j++)
            wmma::load_matrix_sync(bf[j], &Bs[k * 136 + wc * 64 + j * 16], 136);
        #pragma unroll
        for (int i = 0; i < 2; i++)
            #pragma unroll
            for (int j = 0; j < 4; j++)
                wmma::mma_sync(acc[i][j], af[i], bf[j], acc[i][j]);
    }

    __syncthreads();
    #pragma unroll
    for (int i = 0; i < 2; i++)
        #pragma unroll
        for (int j = 0; j < 4; j++)
            wmma::store_matrix_sync(&Stg[(wr * 32 + i * 16) * 136 + wc * 64 + j * 16],
                                    acc[i][j], 136, wmma::mem_row_major);
    __syncthreads();
    #pragma unroll
    for (int i = 0; i < 16; i++) {
        int idx = t + i * 256;
        int r = idx >> 5, c = idx & 31;
        float4 v = *(const float4*)&Stg[r * 136 + c * 4];
        st4h((__half*)&((uint2*)g_Xhh)[(size_t)(row0 + r) * 32 + c], v);
    }
}

// ---------------- gemm_P (side stream): P = Xh @ Wtop + bias (fp32 out) ---------
// 64-row tile, 8 warps x (32x64); B fully resident (128x264 half)
#define P_SMEM (17408 + 67584)
__global__ void __launch_bounds__(256, 2)
gemm_P() {
    extern __shared__ char smc[];
    __half* Axh = (__half*)smc;             // 64 x 136 half
    __half* Bs  = (__half*)(smc + 17408);   // 128 x 264 half
    float* Stg  = (float*)smc;              // 64 x 264 float (reuse, 67584 <= 84992)
    int t = threadIdx.x;
    int warp = t >> 5;
    int row0 = blockIdx.x * 64;

    #pragma unroll
    for (int i = 0; i < 8; i++) {
        int idx = t + i * 256;
        int r = idx >> 5, c = idx & 31;
        *(uint2*)&Axh[r * 136 + c * 4] = ((const uint2*)g_Xhh)[(size_t)(row0 + r) * 32 + c];
    }
    #pragma unroll
    for (int i = 0; i < 32; i++) {
        int idx = t + i * 256;              // 0..8191 uint2
        int r = idx >> 6, c4 = idx & 63;
        *(uint2*)&Bs[r * 264 + c4 * 4] = ((const uint2*)g_Wcomb)[idx];  // top half
    }
    __syncthreads();

    int wr = warp & 1, wc = warp >> 1;      // 32-row x 64-col warp tiles

    wmma::fragment<wmma::accumulator, 16, 16, 16, float> acc[2][4];
    #pragma unroll
    for (int i = 0; i < 2; i++)
        #pragma unroll
        for (int j = 0; j < 4; j++)
            wmma::fill_fragment(acc[i][j], 0.0f);

    #pragma unroll
    for (int k = 0; k < 128; k += 16) {
        wmma::fragment<wmma::matrix_a, 16, 16, 16, __half, wmma::row_major> af[2];
        wmma::fragment<wmma::matrix_b, 16, 16, 16, __half, wmma::row_major> bf[4];
        #pragma unroll
        for (int i = 0; i < 2; i++)
            wmma::load_matrix_sync(af[i], &Axh[(wr * 32 + i * 16) * 136 + k], 136);
        #pragma unroll
        for (int j = 0; j < 4; j++)
            wmma::load_matrix_sync(bf[j], &Bs[k * 264 + wc * 64 + j * 16], 264);
        #pragma unroll
        for (int i = 0; i < 2; i++)
            #pragma unroll
            for (int j = 0; j < 4; j++)
                wmma::mma_sync(acc[i][j], af[i], bf[j], acc[i][j]);
    }

    __syncthreads();
    #pragma unroll
    for (int i = 0; i < 2; i++)
        #pragma unroll
        for (int j = 0; j < 4; j++)
            wmma::store_matrix_sync(&Stg[(wr * 32 + i * 16) * 264 + wc * 64 + j * 16],
                                    acc[i][j], 264, wmma::mem_row_major);
    __syncthreads();
    #pragma unroll
    for (int i = 0; i < 16; i++) {
        int idx = t + i * 256;              // 0..4095 float4
        int r = idx >> 6, c4 = idx & 63;
        float4 v = *(const float4*)&Stg[r * 264 + c4 * 4];
        float4 b = ((const float4*)g_biasf2)[c4];
        v.x += b.x; v.y += b.y; v.z += b.z; v.w += b.w;
        ((float4*)g_P)[(size_t)(row0 + r) * 64 + c4] = v;
    }
}

// ---------------- gates_lx (critical path): acc = P + LX @ Wbot; combine --------
// h = relu( sigmoid(-(z)) * tanh(hpre) ), z = acc cols [0,128), hpre = [128,256)
#define GLX_SMEM 67584
__global__ void __launch_bounds__(256, 2)
gates_lx() {
    extern __shared__ char smc[];
    __half* Alx = (__half*)smc;             // 64 x 136 half
    __half* Bs  = (__half*)(smc + 17408);   // 64 x 264 half (33792)
    float* Stg  = (float*)smc;              // 64 x 264 float (67584, reuse all)
    int t = threadIdx.x;
    int warp = t >> 5;
    int row0 = blockIdx.x * 64;

    #pragma unroll
    for (int i = 0; i < 8; i++) {
        int idx = t + i * 256;
        int r = idx >> 5, c = idx & 31;
        *(uint2*)&Alx[r * 136 + c * 4] = ((const uint2*)g_LXh)[(size_t)(row0 + r) * 32 + c];
    }

    int wr = warp & 1, wc = warp >> 1;

    wmma::fragment<wmma::accumulator, 16, 16, 16, float> acc[2][4];
    #pragma unroll
    for (int i = 0; i < 2; i++)
        #pragma unroll
        for (int j = 0; j < 4; j++)
            wmma::load_matrix_sync(acc[i][j],
                &g_P[(size_t)(row0 + wr * 32 + i * 16) * 256 + wc * 64 + j * 16],
                256, wmma::mem_row_major);

    const uint2* Wbot = (const uint2*)(g_Wcomb + 128 * 256);
    #pragma unroll
    for (int ks = 0; ks < 128; ks += 64) {
        // load Bs slice: rows [ks, ks+64) of Wbot
        #pragma unroll
        for (int i = 0; i < 16; i++) {
            int idx = t + i * 256;          // 0..4095 uint2
            int r = idx >> 6, c4 = idx & 63;
            *(uint2*)&Bs[r * 264 + c4 * 4] = Wbot[(ks + r) * 64 + c4];
        }
        __syncthreads();
        #pragma unroll
        for (int k = 0; k < 64; k += 16) {
            wmma::fragment<wmma::matrix_a, 16, 16, 16, __half, wmma::row_major> af[2];
            wmma::fragment<wmma::matrix_b, 16, 16, 16, __half, wmma::row_major> bf[4];
            #pragma unroll
            for (int i = 0; i < 2; i++)
                wmma::load_matrix_sync(af[i], &Alx[(wr * 32 + i * 16) * 136 + ks + k], 136);
            #pragma unroll
            for (int j = 0; j < 4; j++)
                wmma::load_matrix_sync(bf[j], &Bs[k * 264 + wc * 64 + j * 16], 264);
            #pragma unroll
            for (int i = 0; i < 2; i++)
                #pragma unroll
                for (int j = 0; j < 4; j++)
                    wmma::mma_sync(acc[i][j], af[i], bf[j], acc[i][j]);
        }
        __syncthreads();
    }

    // stage z|hpre to smem (overwrites Alx+Bs), combine cross-warp, emit fp16 h
    #pragma unroll
    for (int i = 0; i < 2; i++)
        #pragma unroll
        for (int j = 0; j < 4; j++)
            wmma::store_matrix_sync(&Stg[(wr * 32 + i * 16) * 264 + wc * 64 + j * 16],
                                    acc[i][j], 264, wmma::mem_row_major);
    __syncthreads();
    #pragma unroll
    for (int i = 0; i < 8; i++) {
        int idx = t + i * 256;              // 0..2047
        int r = idx >> 5, c4 = idx & 31;
        float4 z4 = *(const float4*)&Stg[r * 264 + c4 * 4];
        float4 p4 = *(const float4*)&Stg[r * 264 + 128 + c4 * 4];
        float4 h;
        h.x = fmaxf(tanhf(p4.x) / (1.0f + __expf(z4.x)), 0.0f);
        h.y = fmaxf(tanhf(p4.y) / (1.0f + __expf(z4.y)), 0.0f);
        h.z = fmaxf(tanhf(p4.z) / (1.0f + __expf(z4.z)), 0.0f);
        h.w = fmaxf(tanhf(p4.w) / (1.0f + __expf(z4.w)), 0.0f);
        st4h((__half*)&((uint2*)g_hh)[(size_t)(row0 + r) * 32 + c4], h);
    }
}

// ---------------- decoder: out[e] = dot(h[s]*h[d], pw) + pb (fp16 h) -----------
__global__ void decoder_kernel(const void* __restrict__ eli,
                               const float* __restrict__ post_w,
                               const float* __restrict__ post_b,
                               float* __restrict__ out, int EL, int n_nodes) {
    __shared__ int sh64;
    if (threadIdx.x < 32) {
        int ok = detect64_warp(eli, n_nodes, threadIdx.x);
        if (threadIdx.x == 0) sh64 = ok;
    }
    __syncthreads();
    int is64 = sh64;
    int gw = (blockIdx.x * blockDim.x + threadIdx.x) >> 5;
    int lane = threadIdx.x & 31;
    float4 w0 = ((const float4*)post_w)[lane * 2];
    float4 w1 = ((const float4*)post_w)[lane * 2 + 1];
    float pw0 = w0.x + w0.y, pw1 = w0.z + w0.w;
    float pw2 = w1.x + w1.y, pw3 = w1.z + w1.w;
    float pb = post_b[0] + post_b[1];
    const uint2* H = (const uint2*)g_hh;

    int e0 = gw * 2, e1 = gw * 2 + 1;
    if (e0 >= EL) return;
    bool has1 = (e1 < EL);

    long long s0 = ld_idx(eli, e0, is64);
    long long d0 = ld_idx(eli, (long long)EL + e0, is64);
    long long s1 = has1 ? ld_idx(eli, e1, is64) : s0;
    long long d1 = has1 ? ld_idx(eli, (long long)EL + e1, is64) : d0;

    uint2 av0 = H[(size_t)s0 * 32 + lane];
    uint2 bv0 = H[(size_t)d0 * 32 + lane];
    uint2 av1 = H[(size_t)s1 * 32 + lane];
    uint2 bv1 = H[(size_t)d1 * 32 + lane];

    float2 a00 = __half22float2(*(__half2*)&av0.x);
    float2 a01 = __half22float2(*(__half2*)&av0.y);
    float2 b00 = __half22float2(*(__half2*)&bv0.x);
    float2 b01 = __half22float2(*(__half2*)&bv0.y);
    float acc0 = a00.x * b00.x * pw0 + a00.y * b00.y * pw1
               + a01.x * b01.x * pw2 + a01.y * b01.y * pw3;

    float2 a10 = __half22float2(*(__half2*)&av1.x);
    float2 a11 = __half22float2(*(__half2*)&av1.y);
    float2 b10 = __half22float2(*(__half2*)&bv1.x);
    float2 b11 = __half22float2(*(__half2*)&bv1.y);
    float acc1 = a10.x * b10.x * pw0 + a10.y * b10.y * pw1
               + a11.x * b11.x * pw2 + a11.y * b11.y * pw3;

    #pragma unroll
    for (int o = 16; o > 0; o >>= 1) {
        acc0 += __shfl_xor_sync(0xFFFFFFFFu, acc0, o);
        acc1 += __shfl_xor_sync(0xFFFFFFFFu, acc1, o);
    }
    if (lane == 0) {
        out[e0] = acc0 + pb;
        if (has1) out[e1] = acc1 + pb;
    }
}

// ---------------- launch ----------------
extern "C" void kernel_launch(void* const* d_in, const int* in_sizes, int n_in,
                              void* d_out, int out_size) {
    const float* x      = (const float*)d_in[0];
    const void*  ei     = d_in[1];
    const void*  eli    = d_in[2];
    const float* pre_w  = (const float*)d_in[3];
    const float* pre_b  = (const float*)d_in[4];
    const float* Wx     = (const float*)d_in[5];
    const float* bx     = (const float*)d_in[6];
    const float* Wh     = (const float*)d_in[7];  (void)Wh;  // H0=0 -> only biases matter
    const float* bh     = (const float*)d_in[8];
    const float* post_w = (const float*)d_in[9];
    const float* post_b = (const float*)d_in[10];
    float* out = (float*)d_out;

    int N    = in_sizes[0] / HD;
    int E    = in_sizes[1] / 2;
    int EL   = in_sizes[2] / 2;
    int npad = ((N + 127) / 128) * 128;

    // one-time handle creation (no per-call leaks; deterministic thereafter)
    static cudaStream_t s2 = nullptr;
    static cudaEvent_t evA = nullptr, evB = nullptr, evC = nullptr;
    static bool init_done = false;
    if (!init_done) {
        cudaStreamCreateWithFlags(&s2, cudaStreamNonBlocking);
        cudaEventCreateWithFlags(&evA, cudaEventDisableTiming);
        cudaEventCreateWithFlags(&evB, cudaEventDisableTiming);
        cudaEventCreateWithFlags(&evC, cudaEventDisableTiming);
        cudaFuncSetAttribute(gemm_pre_fp16,
                             cudaFuncAttributeMaxDynamicSharedMemorySize, 100 * 1024);
        cudaFuncSetAttribute(gemm_P,
                             cudaFuncAttributeMaxDynamicSharedMemorySize, 100 * 1024);
        cudaFuncSetAttribute(gates_lx,
                             cudaFuncAttributeMaxDynamicSharedMemorySize, 100 * 1024);
        init_done = true;
    }

    // fork: feature path on s2 (Xh GEMM + weight convert, then P = Xh@Wtop+bias)
    cudaEventRecord(evA, 0);
    cudaStreamWaitEvent(s2, evA, 0);
    gemm_pre_fp16<<<npad / 128, 256, PRE_SMEM, s2>>>(x, pre_w, pre_b,
                                                     Wx, bx, bh, N);        // #1
    cudaEventRecord(evB, s2);        // Xhh + fp16 weights ready
    gemm_P<<<npad / 64, 256, P_SMEM, s2>>>();                               // #2
    cudaEventRecord(evC, s2);        // P ready

    // edge path on the capture stream (memset zeroes out-deg + ELL counts)
    void* p_ints = nullptr;
    cudaGetSymbolAddress(&p_ints, g_ints);
    cudaMemsetAsync(p_ints, 0, (size_t)(2 * NMAX) * sizeof(int));

    fill_ell<<<(E + 255) / 256, 256>>>(ei, E, N);                           // #3

    // spmm needs Xhh (evB) + ELL (stream order)
    cudaStreamWaitEvent(0, evB, 0);
    spmm_ell<<<(npad * 32 + 255) / 256, 256>>>(N, npad);                    // #4 (profiled)

    // gates needs LXh (stream order) + P (evC)
    cudaStreamWaitEvent(0, evC, 0);
    gates_lx<<<npad / 64, 256, GLX_SMEM>>>();                               // #5

    decoder_kernel<<<(EL + 15) / 16, 256>>>(eli, post_w, post_b, out, EL, N);  // #6
}

// round 15
// speedup vs baseline: 1.1673x; 1.1673x over previous
#include <cuda_runtime.h>
#include <cuda_fp16.h>
#include <mma.h>

using namespace nvcuda;

#define NMAX    50000
#define NPADMAX 50176   // ceil(50000/128)*128
#define HD      128
#define EMAX    800000
#define ELLW    96      // ELL row width; P(in-deg >= 96) ~ 1e-25 for Poisson(16)

// ---------------- device scratch (no allocations allowed) ----------------
// g_ints: [0,N): out-degree (src); [NMAX, NMAX+N): ELL in-counts (dst)
__device__ int    g_ints[2 * NMAX];
__device__ int    g_ell[(size_t)NMAX * ELLW];  // ELL: src indices grouped by dst
__device__ __half g_Wxh[4 * 16384];            // fp16 gate weights: z0,z1,h0,h1
__device__ float  g_biasf[2 * HD];             // folded biases: bx[g]+bh[g], g in {z,h}
__device__ __half g_Xhh[(size_t)NPADMAX * HD]; // fp16 Xh
__device__ __half g_LXh[(size_t)NPADMAX * HD]; // fp16 LX = L_hat @ Xh
__device__ __half g_hh [(size_t)NPADMAX * HD]; // fp16 h for decoder

// ---------------- helpers ----------------
__device__ __forceinline__ void st4h(__half* p, float4 v) {
    __half2 a = __floats2half2_rn(v.x, v.y);
    __half2 b = __floats2half2_rn(v.z, v.w);
    uint2 o;
    o.x = *(unsigned*)&a;
    o.y = *(unsigned*)&b;
    *(uint2*)p = o;
}

// edge buffers are declared int64 in the reference, but JAX without x64
// silently yields int32. 32 lanes x 2 int64 reads + ballot: random int32
// pairs combine to values >= N with overwhelming probability.
__device__ __forceinline__ int detect64_warp(const void* p, int n_nodes, int lane) {
    const long long* q = (const long long*)p;
    long long v0 = q[lane];
    long long v1 = q[32 + lane];
    int ok = (v0 >= 0) && (v0 < (long long)n_nodes) &&
             (v1 >= 0) && (v1 < (long long)n_nodes);
    return __all_sync(0xFFFFFFFFu, ok);
}

__device__ __forceinline__ long long ld_idx(const void* p, long long i, int is64) {
    if (is64) return ((const long long*)p)[i];
    return (long long)((const int*)p)[i];
}

// ---------------- ELL build: out-degree + grouped-by-dst src lists, one pass ----
__global__ void fill_ell(const void* __restrict__ ei, int E, int n_nodes) {
    __shared__ int sh64;
    if (threadIdx.x < 32) {
        int ok = detect64_warp(ei, n_nodes, threadIdx.x);
        if (threadIdx.x == 0) sh64 = ok;
    }
    __syncthreads();
    int is64 = sh64;
    int e = blockIdx.x * blockDim.x + threadIdx.x;
    if (e < E) {
        long long s = ld_idx(ei, e, is64);
        long long d = ld_idx(ei, (long long)E + e, is64);
        atomicAdd(&g_ints[s], 1);                       // out-degree
        int slot = atomicAdd(&g_ints[NMAX + d], 1);     // in-count / ELL cursor
        if (slot < ELLW) g_ell[(size_t)d * ELLW + slot] = (int)s;
    }
}

// ---------------- SpMM: LXh[d] = sum -(dinv[s]*dinv[d]) * Xhh[s]  --------------
// warp per row; unroll-8 for memory-level parallelism; dinv inline from out-deg.
#define SPMM_GRP(K) \
    { int s_ = row[j + K]; \
      w_[K] = rsqrtf((float)g_ints[s_]); \
      v_[K] = Xb[(size_t)s_ * 32 + lane]; }
#define SPMM_ACC(K) \
    { float2 f0_ = __half22float2(*(__half2*)&v_[K].x); \
      float2 f1_ = __half22float2(*(__half2*)&v_[K].y); \
      float w__ = dv * w_[K]; \
      acc.x += w__ * f0_.x; acc.y += w__ * f0_.y; \
      acc.z += w__ * f1_.x; acc.w += w__ * f1_.y; }
__global__ void __launch_bounds__(256)
spmm_ell(int n, int npad) {
    int gw = (blockIdx.x * blockDim.x + threadIdx.x) >> 5;
    int lane = threadIdx.x & 31;
    if (gw >= npad) return;
    float4 acc = make_float4(0.f, 0.f, 0.f, 0.f);
    if (gw < n) {
        int od = g_ints[gw];
        float dv = (od > 0) ? -rsqrtf((float)od) : 0.0f;
        int len = g_ints[NMAX + gw];
        if (len > ELLW) len = ELLW;
        const int* row = &g_ell[(size_t)gw * ELLW];
        const uint2* Xb = (const uint2*)g_Xhh;
        float w_[8];
        uint2 v_[8];
        int j = 0;
        for (; j + 7 < len; j += 8) {
            SPMM_GRP(0) SPMM_GRP(1) SPMM_GRP(2) SPMM_GRP(3)
            SPMM_GRP(4) SPMM_GRP(5) SPMM_GRP(6) SPMM_GRP(7)
            SPMM_ACC(0) SPMM_ACC(1) SPMM_ACC(2) SPMM_ACC(3)
            SPMM_ACC(4) SPMM_ACC(5) SPMM_ACC(6) SPMM_ACC(7)
        }
        for (; j + 3 < len; j += 4) {
            SPMM_GRP(0) SPMM_GRP(1) SPMM_GRP(2) SPMM_GRP(3)
            SPMM_ACC(0) SPMM_ACC(1) SPMM_ACC(2) SPMM_ACC(3)
        }
        for (; j < len; j++) {
            int s = row[j];
            float w = dv * rsqrtf((float)g_ints[s]);
            uint2 val = Xb[(size_t)s * 32 + lane];
            float2 f0 = __half22float2(*(__half2*)&val.x);
            float2 f1 = __half22float2(*(__half2*)&val.y);
            acc.x += w * f0.x; acc.y += w * f0.y;
            acc.z += w * f1.x; acc.w += w * f1.y;
        }
    }
    st4h(&g_LXh[(size_t)gw * HD + lane * 4], acc);
}

// ---------------- fp16 GEMM: Xhh = fp16(x @ pre_w + pre_b); blocks 0..64 also
// pre-convert the gate weights to fp16 and fold the gate biases. -----------------
#define PRE_SMEM (34816 + 34816 + 8704)
__global__ void __launch_bounds__(256)
gemm_pre_fp16(const float* __restrict__ x, const float* __restrict__ W,
              const float* __restrict__ bias,
              const float* __restrict__ Wx, const float* __restrict__ bx,
              const float* __restrict__ bh, int n) {
    extern __shared__ char smc[];
    __half* As  = (__half*)smc;             // 128 x 136 half
    __half* Bs  = (__half*)(smc + 34816);   // 128 x 136 half
    float* Bias = (float*)(smc + 69632);    // 16 x 136 float
    float* Stg  = (float*)smc;              // epilogue stage: 128 x 136 float (reuse)
    int t = threadIdx.x;
    int row0 = blockIdx.x * 128;

    // prologue: gate weight fp32->fp16 (chunks z0,z1,h0,h1) + bias fold
    if (blockIdx.x < 64) {
        int idx = blockIdx.x * 256 + t;       // float4 index, 0..16383
        int chunk = idx >> 12;                // 0..3
        int within = idx & 4095;              // float4 within chunk
        int g3 = (chunk < 2) ? 0 : 2;
        int cheb = chunk & 1;
        float4 v = ((const float4*)Wx)[(size_t)(g3 * 2 + cheb) * 4096 + within];
        st4h(&g_Wxh[(size_t)chunk * 16384 + within * 4], v);
    } else if (blockIdx.x == 64 && t < 2 * HD) {
        int g = t >> 7;                       // 0=z, 1=h
        int c = t & 127;
        g_biasf[t] = bx[g * 2 * 128 + c] + bh[g * 2 * 128 + c];
    }

    const float4* x4 = (const float4*)x;
    #pragma unroll
    for (int i = 0; i < 16; i++) {
        int idx = t + i * 256;
        int r = idx >> 5, c = idx & 31;
        float4 v = make_float4(0.f, 0.f, 0.f, 0.f);
        if (row0 + r < n) v = x4[(size_t)(row0 + r) * 32 + c];
        st4h(&As[r * 136 + c * 4], v);
    }
    const float4* W4 = (const float4*)W;
    #pragma unroll
    for (int i = 0; i < 16; i++) {
        int idx = t + i * 256;
        int r = idx >> 5, c = idx & 31;
        st4h(&Bs[r * 136 + c * 4], W4[idx]);
    }
    #pragma unroll
    for (int i = 0; i < 8; i++) {
        int idx = t + i * 256;
        int r = idx >> 7, c = idx & 127;
        Bias[r * 136 + c] = bias[c];
    }
    __syncthreads();

    int warp = t >> 5;
    int wr = warp & 3, wc = warp >> 2;

    wmma::fragment<wmma::accumulator, 16, 16, 16, float> acc[2][4];
    #pragma unroll
    for (int i = 0; i < 2; i++)
        #pragma unroll
        for (int j = 0; j < 4; j++)
            wmma::load_matrix_sync(acc[i][j], &Bias[wc * 64 + j * 16], 136,
                                   wmma::mem_row_major);

    #pragma unroll
    for (int k = 0; k < 128; k += 16) {
        wmma::fragment<wmma::matrix_a, 16, 16, 16, __half, wmma::row_major> af[2];
        wmma::fragment<wmma::matrix_b, 16, 16, 16, __half, wmma::row_major> bf[4];
        #pragma unroll
        for (int i = 0; i < 2; i++)
            wmma::load_matrix_sync(af[i], &As[(wr * 32 + i * 16) * 136 + k], 136);
        #pragma unroll
        for (int j = 0; j < 4; j++)
            wmma::load_matrix_sync(bf[j], &Bs[k * 136 + wc * 64 + j * 16], 136);
        #pragma unroll
        for (int i = 0; i < 2; i++)
            #pragma unroll
            for (int j = 0; j < 4; j++)
                wmma::mma_sync(acc[i][j], af[i], bf[j], acc[i][j]);
    }

    __syncthreads();
    #pragma unroll
    for (int i = 0; i < 2; i++)
        #pragma unroll
        for (int j = 0; j < 4; j++)
            wmma::store_matrix_sync(&Stg[(wr * 32 + i * 16) * 136 + wc * 64 + j * 16],
                                    acc[i][j], 136, wmma::mem_row_major);
    __syncthreads();
    #pragma unroll
    for (int i = 0; i < 16; i++) {
        int idx = t + i * 256;
        int r = idx >> 5, c = idx & 31;
        float4 v = *(const float4*)&Stg[r * 136 + c * 4];
        st4h((__half*)&((uint2*)g_Xhh)[(size_t)(row0 + r) * 32 + c], v);
    }
}

// ---------------- gates GEMM (fp16 tensor cores, pre-converted weights) ----------
// h = relu( sigmoid(-(Xh@Wx00 + LX@Wx01 + b0)) * tanh(Xh@Wx20 + LX@Wx21 + b2) )
// 64-row tile, 8 warps x (32x32), ONE acc array reused across gates, znr in
// packed-half2 registers. 78KB smem + <=128 regs -> 2 CTAs/SM.
#define GAT_SMEM (17408 + 17408 + 34816 + 8704)
__global__ void __launch_bounds__(256, 2)
gates_fp16() {
    extern __shared__ char smc[];
    __half* Axh = (__half*)smc;             // 64 x 136 half
    __half* Alx = (__half*)(smc + 17408);   // 64 x 136 half
    __half* Bs  = (__half*)(smc + 34816);   // 128 x 136 half
    float* Bias = (float*)(smc + 69632);    // 16 x 136 float
    float* Stg  = (float*)smc;              // epilogue: 64 x 136 float (reuse A tiles)
    int t = threadIdx.x;
    int warp = t >> 5;
    int row0 = blockIdx.x * 64;

    // load A tiles: 64 rows x 32 uint2 each
    #pragma unroll
    for (int i = 0; i < 8; i++) {
        int idx = t + i * 256;
        int r = idx >> 5, c = idx & 31;
        *(uint2*)&Axh[r * 136 + c * 4] = ((const uint2*)g_Xhh)[(size_t)(row0 + r) * 32 + c];
        *(uint2*)&Alx[r * 136 + c * 4] = ((const uint2*)g_LXh)[(size_t)(row0 + r) * 32 + c];
    }

    int wr = warp & 1;        // 32-row group
    int wc = warp >> 1;       // 32-col group (4 groups)

    wmma::fragment<wmma::accumulator, 16, 16, 16, float> acc[2][2];
    unsigned znr_p[2][2][4];  // 1-sigmoid(zpre) packed half2 (16 regs)

    #pragma unroll
    for (int g = 0; g < 2; g++) {
        __syncthreads();   // A tiles ready (g=0) / prev gate done with Bs+Bias
        // bias tile (pre-folded), replicated over 16 rows
        #pragma unroll
        for (int i = 0; i < 8; i++) {
            int idx = t + i * 256;
            int r = idx >> 7, c = idx & 127;
            Bias[r * 136 + c] = g_biasf[g * 128 + c];
        }
        // weight chunk 0 (fp16, pre-converted)
        {
            const uint2* B4 = (const uint2*)(g_Wxh + (size_t)(g * 2) * 16384);
            #pragma unroll
            for (int i = 0; i < 16; i++) {
                int idx = t + i * 256;
                int r = idx >> 5, c = idx & 31;
                *(uint2*)&Bs[r * 136 + c * 4] = B4[idx];
            }
        }
        __syncthreads();

        #pragma unroll
        for (int i = 0; i < 2; i++)
            #pragma unroll
            for (int j = 0; j < 2; j++)
                wmma::load_matrix_sync(acc[i][j], &Bias[wc * 32 + j * 16], 136,
                                       wmma::mem_row_major);

        #pragma unroll
        for (int c2 = 0; c2 < 2; c2++) {
            if (c2 == 1) {
                __syncthreads();   // done reading chunk 0
                const uint2* B4b = (const uint2*)(g_Wxh + (size_t)(g * 2 + 1) * 16384);
                #pragma unroll
                for (int i = 0; i < 16; i++) {
                    int idx = t + i * 256;
                    int r = idx >> 5, c = idx & 31;
                    *(uint2*)&Bs[r * 136 + c * 4] = B4b[idx];
                }
                __syncthreads();
            }
            const __half* Asrc = (c2 == 0) ? Axh : Alx;
            #pragma unroll
            for (int k = 0; k < 128; k += 16) {
                wmma::fragment<wmma::matrix_a, 16, 16, 16, __half, wmma::row_major> af[2];
                wmma::fragment<wmma::matrix_b, 16, 16, 16, __half, wmma::row_major> bf[2];
                #pragma unroll
                for (int i = 0; i < 2; i++)
                    wmma::load_matrix_sync(af[i], &Asrc[(wr * 32 + i * 16) * 136 + k], 136);
                #pragma unroll
                for (int j = 0; j < 2; j++)
                    wmma::load_matrix_sync(bf[j], &Bs[k * 136 + wc * 32 + j * 16], 136);
                #pragma unroll
                for (int i = 0; i < 2; i++)
                    #pragma unroll
                    for (int j = 0; j < 2; j++)
                        wmma::mma_sync(acc[i][j], af[i], bf[j], acc[i][j]);
            }
        }

        if (g == 0) {
            // znr = 1/(1+exp(zpre)), packed into half2 regs (frees acc for gate h)
            #pragma unroll
            for (int i = 0; i < 2; i++)
                #pragma unroll
                for (int j = 0; j < 2; j++)
                    #pragma unroll
                    for (int e = 0; e < 4; e++) {
                        float z0 = 1.0f / (1.0f + __expf(acc[i][j].x[2 * e]));
                        float z1 = 1.0f / (1.0f + __expf(acc[i][j].x[2 * e + 1]));
                        __half2 hp = __floats2half2_rn(z0, z1);
                        znr_p[i][j][e] = *(unsigned*)&hp;
                    }
        }
    }

    // h = relu(znr * tanh(hpre)); stage fp32 in smem (over A tiles), emit fp16
    #pragma unroll
    for (int i = 0; i < 2; i++)
        #pragma unroll
        for (int j = 0; j < 2; j++)
            #pragma unroll
            for (int e = 0; e < 8; e++) {
                __half2 hp = *(__half2*)&znr_p[i][j][e >> 1];
                float2 zf = __half22float2(hp);
                float znr = (e & 1) ? zf.y : zf.x;
                float ht = tanhf(acc[i][j].x[e]);
                acc[i][j].x[e] = fmaxf(znr * ht, 0.0f);
            }
    __syncthreads();   // all warps done reading A tiles
    #pragma unroll
    for (int i = 0; i < 2; i++)
        #pragma unroll
        for (int j = 0; j < 2; j++)
            wmma::store_matrix_sync(&Stg[(wr * 32 + i * 16) * 136 + wc * 32 + j * 16],
                                    acc[i][j], 136, wmma::mem_row_major);
    __syncthreads();
    #pragma unroll
    for (int i = 0; i < 8; i++) {
        int idx = t + i * 256;
        int r = idx >> 5, c = idx & 31;
        float4 v = *(const float4*)&Stg[r * 136 + c * 4];
        st4h((__half*)&((uint2*)g_hh)[(size_t)(row0 + r) * 32 + c], v);
    }
}

// ---------------- decoder: out[e] = dot(h[s]*h[d], pw) + pb (fp16 h) -----------
__global__ void decoder_kernel(const void* __restrict__ eli,
                               const float* __restrict__ post_w,
                               const float* __restrict__ post_b,
                               float* __restrict__ out, int EL, int n_nodes) {
    __shared__ int sh64;
    if (threadIdx.x < 32) {
        int ok = detect64_warp(eli, n_nodes, threadIdx.x);
        if (threadIdx.x == 0) sh64 = ok;
    }
    __syncthreads();
    int is64 = sh64;
    int gw = (blockIdx.x * blockDim.x + threadIdx.x) >> 5;
    int lane = threadIdx.x & 31;
    float4 w0 = ((const float4*)post_w)[lane * 2];
    float4 w1 = ((const float4*)post_w)[lane * 2 + 1];
    float pw0 = w0.x + w0.y, pw1 = w0.z + w0.w;
    float pw2 = w1.x + w1.y, pw3 = w1.z + w1.w;
    float pb = post_b[0] + post_b[1];
    const uint2* H = (const uint2*)g_hh;

    int e0 = gw * 2, e1 = gw * 2 + 1;
    if (e0 >= EL) return;
    bool has1 = (e1 < EL);

    long long s0 = ld_idx(eli, e0, is64);
    long long d0 = ld_idx(eli, (long long)EL + e0, is64);
    long long s1 = has1 ? ld_idx(eli, e1, is64) : s0;
    long long d1 = has1 ? ld_idx(eli, (long long)EL + e1, is64) : d0;

    uint2 av0 = H[(size_t)s0 * 32 + lane];
    uint2 bv0 = H[(size_t)d0 * 32 + lane];
    uint2 av1 = H[(size_t)s1 * 32 + lane];
    uint2 bv1 = H[(size_t)d1 * 32 + lane];

    float2 a00 = __half22float2(*(__half2*)&av0.x);
    float2 a01 = __half22float2(*(__half2*)&av0.y);
    float2 b00 = __half22float2(*(__half2*)&bv0.x);
    float2 b01 = __half22float2(*(__half2*)&bv0.y);
    float acc0 = a00.x * b00.x * pw0 + a00.y * b00.y * pw1
               + a01.x * b01.x * pw2 + a01.y * b01.y * pw3;

    float2 a10 = __half22float2(*(__half2*)&av1.x);
    float2 a11 = __half22float2(*(__half2*)&av1.y);
    float2 b10 = __half22float2(*(__half2*)&bv1.x);
    float2 b11 = __half22float2(*(__half2*)&bv1.y);
    float acc1 = a10.x * b10.x * pw0 + a10.y * b10.y * pw1
               + a11.x * b11.x * pw2 + a11.y * b11.y * pw3;

    #pragma unroll
    for (int o = 16; o > 0; o >>= 1) {
        acc0 += __shfl_xor_sync(0xFFFFFFFFu, acc0, o);
        acc1 += __shfl_xor_sync(0xFFFFFFFFu, acc1, o);
    }
    if (lane == 0) {
        out[e0] = acc0 + pb;
        if (has1) out[e1] = acc1 + pb;
    }
}

// ---------------- launch ----------------
extern "C" void kernel_launch(void* const* d_in, const int* in_sizes, int n_in,
                              void* d_out, int out_size) {
    const float* x      = (const float*)d_in[0];
    const void*  ei     = d_in[1];
    const void*  eli    = d_in[2];
    const float* pre_w  = (const float*)d_in[3];
    const float* pre_b  = (const float*)d_in[4];
    const float* Wx     = (const float*)d_in[5];
    const float* bx     = (const float*)d_in[6];
    const float* Wh     = (const float*)d_in[7];  (void)Wh;  // H0=0 -> only biases matter
    const float* bh     = (const float*)d_in[8];
    const float* post_w = (const float*)d_in[9];
    const float* post_b = (const float*)d_in[10];
    float* out = (float*)d_out;

    int N    = in_sizes[0] / HD;
    int E    = in_sizes[1] / 2;
    int EL   = in_sizes[2] / 2;
    int npad = ((N + 127) / 128) * 128;

    // one-time handle creation (no per-call leaks; deterministic thereafter)
    static cudaStream_t s2 = nullptr;
    static cudaEvent_t evA = nullptr, evB = nullptr;
    static bool init_done = false;
    if (!init_done) {
        cudaStreamCreateWithFlags(&s2, cudaStreamNonBlocking);
        cudaEventCreateWithFlags(&evA, cudaEventDisableTiming);
        cudaEventCreateWithFlags(&evB, cudaEventDisableTiming);
        cudaFuncSetAttribute(gemm_pre_fp16,
                             cudaFuncAttributeMaxDynamicSharedMemorySize, 100 * 1024);
        cudaFuncSetAttribute(gates_fp16,
                             cudaFuncAttributeMaxDynamicSharedMemorySize, 100 * 1024);
        init_done = true;
    }

    // fork: feature path (Xh GEMM + inline weight convert) on s2
    cudaEventRecord(evA, 0);
    cudaStreamWaitEvent(s2, evA, 0);
    gemm_pre_fp16<<<npad / 128, 256, PRE_SMEM, s2>>>(x, pre_w, pre_b,
                                                     Wx, bx, bh, N);        // #1
    cudaEventRecord(evB, s2);        // Xhh + fp16 weights + biases ready

    // edge path on the capture stream (memset zeroes out-deg + ELL counts)
    void* p_ints = nullptr;
    cudaGetSymbolAddress(&p_ints, g_ints);
    cudaMemsetAsync(p_ints, 0, (size_t)(2 * NMAX) * sizeof(int));

    fill_ell<<<(E + 255) / 256, 256>>>(ei, E, N);                           // #2

    // spmm needs Xhh (evB) + ELL (stream order)
    cudaStreamWaitEvent(0, evB, 0);
    spmm_ell<<<(npad * 32 + 255) / 256, 256>>>(N, npad);                    // #3

    gates_fp16<<<npad / 64, 256, GAT_SMEM>>>();                             // #4 (profiled)

    decoder_kernel<<<(EL + 15) / 16, 256>>>(eli, post_w, post_b, out, EL, N);  // #5
}